// round 14
// baseline (speedup 1.0000x reference)
#include <cuda_runtime.h>
#include <cuda_bf16.h>
#include <cstdint>
#include <math.h>

// ---------------- problem constants ----------------
#define NB  8
#define CC  1024
#define CID 512
#define NN  3136
#define ROWS_TOT (NB * NN)
#define NTILE_M 25                 // ceil(3136/128)
#define BN_CHUNKS (NB * NTILE_M)   // 200

// ---------------- device scratch ----------------
static constexpr size_t P_X = (size_t)NB * NN * CC;
static constexpr size_t P_P = (size_t)NB * NN * CID;
static constexpr size_t P_W = (size_t)CID * CC;
static constexpr size_t P_F = (size_t)NB * NN * NN;

__device__ __nv_bfloat16 g_xs1[2 * P_X];
__device__ __nv_bfloat16 g_xs2[2 * P_X];
__device__ __nv_bfloat16 g_thw[2 * P_W];
__device__ __nv_bfloat16 g_phw[2 * P_W];
__device__ __nv_bfloat16 g_gw [2 * P_W];
__device__ __nv_bfloat16 g_wzw[2 * P_W];
__device__ __nv_bfloat16 g_ths[2 * P_P];
__device__ __nv_bfloat16 g_phs[2 * P_P];
__device__ __nv_bfloat16 g_gTs[2 * P_P];
__device__ __nv_bfloat16 g_ys [2 * P_P];
__device__ float g_f[P_F];
__device__ __nv_bfloat16 g_as[2 * P_F];
__device__ float g_wy[(size_t)NB * NN * CC];
__device__ float g_part[(size_t)BN_CHUNKS * CC * 2];
__device__ float g_ab[CC * 2];

// ---------------- mma / ldmatrix / cp.async wrappers ----------------
__device__ __forceinline__ void mma_bf16(float* c, const uint32_t* a,
                                         uint32_t b0, uint32_t b1)
{
    asm volatile(
        "mma.sync.aligned.m16n8k16.row.col.f32.bf16.bf16.f32 "
        "{%0,%1,%2,%3}, {%4,%5,%6,%7}, {%8,%9}, {%0,%1,%2,%3};"
        : "+f"(c[0]), "+f"(c[1]), "+f"(c[2]), "+f"(c[3])
        : "r"(a[0]), "r"(a[1]), "r"(a[2]), "r"(a[3]), "r"(b0), "r"(b1));
}

#define LDSM_X4(r, addr) \
    asm volatile("ldmatrix.sync.aligned.m8n8.x4.shared.b16 {%0,%1,%2,%3}, [%4];" \
        : "=r"((r)[0]), "=r"((r)[1]), "=r"((r)[2]), "=r"((r)[3]) : "r"(addr))

__device__ __forceinline__ void cp16(uint32_t dst, const void* src, int srcsize)
{
    asm volatile("cp.async.cg.shared.global [%0], [%1], 16, %2;"
        :: "r"(dst), "l"(src), "r"(srcsize));
}
#define CP_COMMIT() asm volatile("cp.async.commit_group;" ::: "memory")
#define CP_WAIT(n)  asm volatile("cp.async.wait_group %0;" :: "n"(n) : "memory")

// ---------------- GEMM tiling: CTA 128x128, 4 warps (64x64 each), K-step 32 ----
#define STAGES 4
#define ROW_BYTES 80
#define A_BYTES (128 * ROW_BYTES)
#define STAGE_BYTES (2 * A_BYTES)
#define SMEM_BYTES (STAGES * STAGE_BYTES)   // 81920

// =====================================================================
// GEMM body: D(M x N) = 3-pass split-bf16 A(M,K) * B(N,K)^T
//   pass 0: A.hi*B.hi   pass 1: A.hi*B.lo   pass 2: A.lo*B.hi
// BIAS: 0 none, 1 col, 2 row.  BN: per-column (sum,sumsq) partials.
// 128 threads, warp tile 64x64 (acc 128 regs/thread), 2 CTAs/SM.
// =====================================================================
template <int BIAS, bool BN>
__device__ __forceinline__ void gemm_body(
    uint8_t* smraw,
    const __nv_bfloat16* __restrict__ A, int lda, size_t planeA2,
    const __nv_bfloat16* __restrict__ B, int ldb, size_t planeB2,
    int M, int N, int K,
    const float* __restrict__ bias,
    float* __restrict__ Cfb,
    __nv_bfloat16* __restrict__ Chb, __nv_bfloat16* __restrict__ Clb,
    int ldc, int m0, int n0, float* __restrict__ bnPart)
{
    const uint32_t smBase = (uint32_t)__cvta_generic_to_shared(smraw);
    const int tid  = threadIdx.x;            // 0..127
    const int wid  = tid >> 5;               // 0..3
    const int lane = tid & 31;
    const int gid  = lane >> 2;
    const int tig  = lane & 3;
    const int warp_m = (wid & 1) * 64;
    const int warp_n = (wid >> 1) * 64;

    // loaders: each thread owns one A row and one B row (4x cp16 each)
    const int aok = ((m0 + tid) < M) ? 16 : 0;
    const int bok = ((n0 + tid) < N) ? 16 : 0;
    const char* aRow = (const char*)(A + (size_t)(m0 + tid) * lda);
    const char* bRow = (const char*)(B + (size_t)(n0 + tid) * ldb);
    const uint32_t sA = tid * ROW_BYTES;
    const uint32_t sB = A_BYTES + tid * ROW_BYTES;

    const int kPerPass = K >> 5;
    const int nIter = 3 * kPerPass;

    const uint32_t aOff = (uint32_t)((warp_m + (lane & 15)) * ROW_BYTES + (lane >> 4) * 16);
    const uint32_t bOff = (uint32_t)(A_BYTES + (warp_n + (lane & 15)) * ROW_BYTES + (lane >> 4) * 16);

    float acc[4][8][4];
#pragma unroll
    for (int i = 0; i < 4; i++)
#pragma unroll
        for (int j = 0; j < 8; j++)
#pragma unroll
            for (int q = 0; q < 4; q++) acc[i][j][q] = 0.f;

    auto issue_stage = [&](int idx) {
        const int p  = idx / kPerPass;
        const int kc = idx - p * kPerPass;
        const size_t offA = (p == 2) ? planeA2 : 0;
        const size_t offB = (p == 1) ? planeB2 : 0;
        const uint32_t st = smBase + (uint32_t)(idx % STAGES) * STAGE_BYTES;
        const char* ga = aRow + offA + kc * 64;
        const char* gb = bRow + offB + kc * 64;
        cp16(st + sA,      ga,      aok);
        cp16(st + sA + 16, ga + 16, aok);
        cp16(st + sA + 32, ga + 32, aok);
        cp16(st + sA + 48, ga + 48, aok);
        cp16(st + sB,      gb,      bok);
        cp16(st + sB + 16, gb + 16, bok);
        cp16(st + sB + 32, gb + 32, bok);
        cp16(st + sB + 48, gb + 48, bok);
        CP_COMMIT();
    };

#pragma unroll
    for (int s = 0; s < STAGES - 1; s++) issue_stage(s);

    for (int it = 0; it < nIter; ++it) {
        CP_WAIT(STAGES - 2);
        __syncthreads();
        if (it + STAGES - 1 < nIter) issue_stage(it + STAGES - 1);
        else CP_COMMIT();

        const uint32_t st = smBase + (uint32_t)(it % STAGES) * STAGE_BYTES;
#pragma unroll
        for (int ks = 0; ks < 2; ks++) {
            uint32_t b[4][4];
#pragma unroll
            for (int q = 0; q < 4; q++)
                LDSM_X4(b[q], st + bOff + q * 1280 + ks * 32);
#pragma unroll
            for (int mf = 0; mf < 4; mf++) {
                uint32_t a[4];
                LDSM_X4(a, st + aOff + mf * 1280 + ks * 32);
#pragma unroll
                for (int q = 0; q < 4; q++) {
                    mma_bf16(acc[mf][2 * q + 0], a, b[q][0], b[q][2]);
                    mma_bf16(acc[mf][2 * q + 1], a, b[q][1], b[q][3]);
                }
            }
        }
    }

    // ---------------- epilogue ----------------
    float bs[16], bs2[16];
    if (BN) {
#pragma unroll
        for (int j = 0; j < 16; j++) { bs[j] = 0.f; bs2[j] = 0.f; }
    }

#pragma unroll
    for (int mf = 0; mf < 4; mf++) {
#pragma unroll
        for (int nf = 0; nf < 8; nf++) {
            const int col = n0 + warp_n + nf * 8 + tig * 2;
            if (col >= N) continue;
            float bcol0 = 0.f, bcol1 = 0.f;
            if (BIAS == 1) { bcol0 = bias[col]; bcol1 = bias[col + 1]; }
#pragma unroll
            for (int half = 0; half < 2; half++) {
                const int row = m0 + warp_m + mf * 16 + gid + half * 8;
                if (row >= M) continue;
                float v0 = acc[mf][nf][half * 2 + 0];
                float v1 = acc[mf][nf][half * 2 + 1];
                if (BIAS == 1) { v0 += bcol0; v1 += bcol1; }
                if (BIAS == 2) { float br = bias[row]; v0 += br; v1 += br; }
                if (BN) {
                    bs[nf * 2 + 0] += v0;  bs2[nf * 2 + 0] += v0 * v0;
                    bs[nf * 2 + 1] += v1;  bs2[nf * 2 + 1] += v1 * v1;
                }
                const size_t o = (size_t)row * ldc + col;
                if (Cfb) {
                    *(float2*)(Cfb + o) = make_float2(v0, v1);
                } else {
                    __nv_bfloat16 h0 = __float2bfloat16(v0);
                    __nv_bfloat16 h1 = __float2bfloat16(v1);
                    __nv_bfloat162 hh, ll;
                    hh.x = h0; hh.y = h1;
                    ll.x = __float2bfloat16(v0 - __bfloat162float(h0));
                    ll.y = __float2bfloat16(v1 - __bfloat162float(h1));
                    *(__nv_bfloat162*)(Chb + o) = hh;
                    *(__nv_bfloat162*)(Clb + o) = ll;
                }
            }
        }
    }

    if (BN) {
        // lane-reduce over gid -> lanes 0..3 hold column partials
#pragma unroll
        for (int j = 0; j < 16; j++) {
#pragma unroll
            for (int off = 4; off < 32; off <<= 1) {
                bs[j]  += __shfl_xor_sync(0xffffffffu, bs[j],  off);
                bs2[j] += __shfl_xor_sync(0xffffffffu, bs2[j], off);
            }
        }
        __syncthreads();
        float* sum0 = (float*)smraw;     // [2][128] sums, then [2][128] sumsq
        float* sq0  = sum0 + 256;
        if (lane < 4) {
#pragma unroll
            for (int nf = 0; nf < 8; nf++) {
#pragma unroll
                for (int par = 0; par < 2; par++) {
                    int c = warp_n + nf * 8 + tig * 2 + par;   // 0..127
                    sum0[(wid & 1) * 128 + c] = bs[nf * 2 + par];
                    sq0 [(wid & 1) * 128 + c] = bs2[nf * 2 + par];
                }
            }
        }
        __syncthreads();
        {
            float s  = sum0[tid] + sum0[128 + tid];
            float s2 = sq0[tid]  + sq0[128 + tid];
            bnPart[(size_t)(n0 + tid) * 2 + 0] = s;
            bnPart[(size_t)(n0 + tid) * 2 + 1] = s2;
        }
    }
}

// =====================================================================
// kernels wrapping gemm_body
// =====================================================================
__global__ void __launch_bounds__(128, 2)
proj_gemm(const __nv_bfloat16* __restrict__ xs1, const __nv_bfloat16* __restrict__ xs2,
          const __nv_bfloat16* __restrict__ thw, const __nv_bfloat16* __restrict__ phw,
          const __nv_bfloat16* __restrict__ gw,
          const float* __restrict__ th_b, const float* __restrict__ ph_b,
          const float* __restrict__ g_b,
          __nv_bfloat16* __restrict__ ths, __nv_bfloat16* __restrict__ phs,
          __nv_bfloat16* __restrict__ gTs)
{
    extern __shared__ __align__(16) uint8_t smraw[];
    const int z = blockIdx.z;
    const int which = z % 3;
    const int bz = z / 3;
    const size_t bX = (size_t)NN * CC;
    const size_t bP = (size_t)NN * CID;

    if (which == 0) {
        gemm_body<1, false>(smraw,
            xs1 + (size_t)bz * bX, CC, P_X * 2,
            thw, CC, P_W * 2,
            NN, CID, CC, th_b,
            nullptr, ths + (size_t)bz * bP, ths + P_P + (size_t)bz * bP,
            CID, blockIdx.y * 128, blockIdx.x * 128, nullptr);
    } else if (which == 1) {
        gemm_body<1, false>(smraw,
            xs2 + (size_t)bz * bX, CC, P_X * 2,
            phw, CC, P_W * 2,
            NN, CID, CC, ph_b,
            nullptr, phs + (size_t)bz * bP, phs + P_P + (size_t)bz * bP,
            CID, blockIdx.y * 128, blockIdx.x * 128, nullptr);
    } else {
        gemm_body<2, false>(smraw,
            gw, CC, P_W * 2,
            xs2 + (size_t)bz * bX, CC, P_X * 2,
            CID, NN, CC, g_b,
            nullptr, gTs + (size_t)bz * bP, gTs + P_P + (size_t)bz * bP,
            NN, blockIdx.x * 128, blockIdx.y * 128, nullptr);
    }
}

template <int BIAS, bool BN>
__global__ void __launch_bounds__(128, 2)
hm_gemm(const __nv_bfloat16* __restrict__ A, int lda, size_t batchA, size_t planeA,
        const __nv_bfloat16* __restrict__ B, int ldb, size_t batchB, size_t planeB,
        int M, int N, int K,
        const float* __restrict__ bias,
        float* __restrict__ Cf,
        __nv_bfloat16* __restrict__ Chi, __nv_bfloat16* __restrict__ Clo,
        int ldc, size_t batchC, float* __restrict__ bnPart)
{
    extern __shared__ __align__(16) uint8_t smraw[];
    const int bz = blockIdx.z;
    const int m0 = blockIdx.y * 128;
    const int n0 = blockIdx.x * 128;
    float* bp = nullptr;
    if (BN) bp = bnPart + ((size_t)bz * NTILE_M + blockIdx.y) * CC * 2;
    gemm_body<BIAS, BN>(smraw,
        A + (size_t)bz * batchA, lda, planeA * 2,
        B + (size_t)bz * batchB, ldb, planeB * 2,
        M, N, K, bias,
        Cf ? Cf + (size_t)bz * batchC : nullptr,
        Chi ? Chi + (size_t)bz * batchC : nullptr,
        Clo ? Clo + (size_t)bz * batchC : nullptr,
        ldc, m0, n0, bp);
}

// =====================================================================
// NCHW -> NHWC transpose + bf16 hi/lo split of x1 and x2
// =====================================================================
__global__ void __launch_bounds__(256)
split_tr(const float* __restrict__ x1, const float* __restrict__ x2,
         __nv_bfloat16* __restrict__ hi1, __nv_bfloat16* __restrict__ hi2)
{
    __shared__ float t[32][33];
    const int z = blockIdx.z;
    const int b = z & 7;
    const float* x = (z < NB) ? x1 : x2;
    __nv_bfloat16* hi = (z < NB) ? hi1 : hi2;
    const int n0 = blockIdx.x * 32;
    const int c0 = blockIdx.y * 32;
    const int tx = threadIdx.x, ty = threadIdx.y;

    for (int i = ty; i < 32; i += 8)
        t[i][tx] = x[((size_t)b * CC + c0 + i) * NN + n0 + tx];
    __syncthreads();
    for (int i = ty; i < 32; i += 8) {
        float v = t[tx][i];
        size_t o = ((size_t)b * NN + n0 + i) * CC + c0 + tx;
        __nv_bfloat16 h = __float2bfloat16(v);
        hi[o] = h;
        hi[P_X + o] = __float2bfloat16(v - __bfloat162float(h));
    }
}

__global__ void __launch_bounds__(256)
split_w4(const float* __restrict__ w0, const float* __restrict__ w1,
         const float* __restrict__ w2, const float* __restrict__ w3,
         __nv_bfloat16* __restrict__ h0, __nv_bfloat16* __restrict__ h1,
         __nv_bfloat16* __restrict__ h2, __nv_bfloat16* __restrict__ h3)
{
    const int which = blockIdx.y;
    const float* w = which == 0 ? w0 : which == 1 ? w1 : which == 2 ? w2 : w3;
    __nv_bfloat16* h = which == 0 ? h0 : which == 1 ? h1 : which == 2 ? h2 : h3;
    int i = blockIdx.x * 256 + threadIdx.x;
    if (i < (int)P_W) {
        float v = w[i];
        __nv_bfloat16 hh = __float2bfloat16(v);
        h[i] = hh;
        h[P_W + i] = __float2bfloat16(v - __bfloat162float(hh));
    }
}

// =====================================================================
// Row softmax over NN (vectorized), writes split bf16 attn
// =====================================================================
#define NN4 (NN / 4)
__global__ void __launch_bounds__(256)
softmax_split(const float* __restrict__ F, __nv_bfloat16* __restrict__ hi,
              __nv_bfloat16* __restrict__ lo)
{
    __shared__ float4 buf[NN4];
    __shared__ float red[256];
    const size_t row = blockIdx.x;
    const float4* __restrict__ p = (const float4*)(F + row * (size_t)NN);
    const int t = threadIdx.x;

    float m = -3.402823466e38f;
    for (int i = t; i < NN4; i += 256) {
        float4 v = p[i];
        buf[i] = v;
        m = fmaxf(fmaxf(m, fmaxf(v.x, v.y)), fmaxf(v.z, v.w));
    }
    red[t] = m; __syncthreads();
    for (int s = 128; s > 0; s >>= 1) {
        if (t < s) red[t] = fmaxf(red[t], red[t + s]);
        __syncthreads();
    }
    m = red[0];
    __syncthreads();

    float sum = 0.f;
    for (int i = t; i < NN4; i += 256) {
        float4 v = buf[i];
        v.x = __expf(v.x - m); v.y = __expf(v.y - m);
        v.z = __expf(v.z - m); v.w = __expf(v.w - m);
        buf[i] = v;
        sum += (v.x + v.y) + (v.z + v.w);
    }
    red[t] = sum; __syncthreads();
    for (int s = 128; s > 0; s >>= 1) {
        if (t < s) red[t] += red[t + s];
        __syncthreads();
    }
    const float inv = 1.f / red[0];
    __nv_bfloat162* __restrict__ hp = (__nv_bfloat162*)(hi + row * (size_t)NN);
    __nv_bfloat162* __restrict__ lp = (__nv_bfloat162*)(lo + row * (size_t)NN);
    for (int i = t; i < NN4; i += 256) {
        float4 v = buf[i];
        float a0 = v.x * inv, a1 = v.y * inv, a2 = v.z * inv, a3 = v.w * inv;
        __nv_bfloat162 h0, h1, l0, l1;
        h0.x = __float2bfloat16(a0); h0.y = __float2bfloat16(a1);
        h1.x = __float2bfloat16(a2); h1.y = __float2bfloat16(a3);
        l0.x = __float2bfloat16(a0 - __bfloat162float(h0.x));
        l0.y = __float2bfloat16(a1 - __bfloat162float(h0.y));
        l1.x = __float2bfloat16(a2 - __bfloat162float(h1.x));
        l1.y = __float2bfloat16(a3 - __bfloat162float(h1.y));
        hp[i * 2] = h0; hp[i * 2 + 1] = h1;
        lp[i * 2] = l0; lp[i * 2 + 1] = l1;
    }
}

// =====================================================================
// BN finalize over fused partials
// =====================================================================
__global__ void __launch_bounds__(256)
bn_finalize(const float* __restrict__ gamma, const float* __restrict__ beta)
{
    int c = blockIdx.x * 256 + threadIdx.x;
    float s = 0.f, s2 = 0.f;
    for (int ch = 0; ch < BN_CHUNKS; ch++) {
        s  += g_part[((size_t)ch * CC + c) * 2 + 0];
        s2 += g_part[((size_t)ch * CC + c) * 2 + 1];
    }
    const float invR = 1.f / (float)ROWS_TOT;
    float mu  = s * invR;
    float var = s2 * invR - mu * mu;
    float a = gamma[c] * rsqrtf(var + 1e-5f);
    g_ab[c * 2 + 0] = a;
    g_ab[c * 2 + 1] = beta[c] - mu * a;
}

// =====================================================================
// normalize + residual + NHWC->NCHW transpose
// =====================================================================
__global__ void __launch_bounds__(256)
out_kernel(const float* __restrict__ wy, const float* __restrict__ x1,
           float* __restrict__ out)
{
    __shared__ float tile[32][33];
    int b  = blockIdx.z;
    int n0 = blockIdx.x * 32;
    int c0 = blockIdx.y * 32;
    int tx = threadIdx.x, ty = threadIdx.y;

    for (int i = ty; i < 32; i += 8) {
        int c = c0 + tx, n = n0 + i;
        float v = wy[((size_t)b * NN + n) * CC + c];
        tile[i][tx] = v * g_ab[c * 2 + 0] + g_ab[c * 2 + 1];
    }
    __syncthreads();
    for (int i = ty; i < 32; i += 8) {
        int c = c0 + i, n = n0 + tx;
        size_t idx = ((size_t)b * CC + c) * (size_t)NN + n;
        out[idx] = tile[tx][i] + x1[idx];
    }
}

// =====================================================================
// launcher
// =====================================================================
extern "C" void kernel_launch(void* const* d_in, const int* in_sizes, int n_in,
                              void* d_out, int out_size)
{
    const float* x1   = (const float*)d_in[0];
    const float* x2   = (const float*)d_in[1];
    const float* g_w  = (const float*)d_in[2];
    const float* g_b  = (const float*)d_in[3];
    const float* th_w = (const float*)d_in[4];
    const float* th_b = (const float*)d_in[5];
    const float* ph_w = (const float*)d_in[6];
    const float* ph_b = (const float*)d_in[7];
    const float* wz_w = (const float*)d_in[8];
    const float* wz_b = (const float*)d_in[9];
    const float* gam  = (const float*)d_in[10];
    const float* bet  = (const float*)d_in[11];
    float* out = (float*)d_out;

    cudaFuncSetAttribute((const void*)proj_gemm,
                         cudaFuncAttributeMaxDynamicSharedMemorySize, SMEM_BYTES);
    cudaFuncSetAttribute((const void*)hm_gemm<0, false>,
                         cudaFuncAttributeMaxDynamicSharedMemorySize, SMEM_BYTES);
    cudaFuncSetAttribute((const void*)hm_gemm<1, true>,
                         cudaFuncAttributeMaxDynamicSharedMemorySize, SMEM_BYTES);

    __nv_bfloat16 *xs1, *xs2, *thw, *phw, *gw, *wzw, *ths, *phs, *gTs, *ys, *as;
    float *f, *wy, *part;
    cudaGetSymbolAddress((void**)&xs1, g_xs1);
    cudaGetSymbolAddress((void**)&xs2, g_xs2);
    cudaGetSymbolAddress((void**)&thw, g_thw);
    cudaGetSymbolAddress((void**)&phw, g_phw);
    cudaGetSymbolAddress((void**)&gw,  g_gw);
    cudaGetSymbolAddress((void**)&wzw, g_wzw);
    cudaGetSymbolAddress((void**)&ths, g_ths);
    cudaGetSymbolAddress((void**)&phs, g_phs);
    cudaGetSymbolAddress((void**)&gTs, g_gTs);
    cudaGetSymbolAddress((void**)&ys,  g_ys);
    cudaGetSymbolAddress((void**)&as,  g_as);
    cudaGetSymbolAddress((void**)&f,   g_f);
    cudaGetSymbolAddress((void**)&wy,  g_wy);
    cudaGetSymbolAddress((void**)&part, g_part);

    dim3 blk256(256);
    dim3 blk128(128);
    dim3 blkT(32, 8);

    split_tr<<<dim3(NN / 32, CC / 32, 2 * NB), blkT>>>(x1, x2, xs1, xs2);
    split_w4<<<dim3((int)((P_W + 255) / 256), 4), blk256>>>(
        th_w, ph_w, g_w, wz_w, thw, phw, gw, wzw);

    const size_t bP = (size_t)NN * CID;
    const size_t bF = (size_t)NN * NN;

    proj_gemm<<<dim3(CID / 128, NTILE_M, NB * 3), blk128, SMEM_BYTES>>>(
        xs1, xs2, thw, phw, gw, th_b, ph_b, g_b, ths, phs, gTs);

    hm_gemm<0, false><<<dim3(NTILE_M, NTILE_M, NB), blk128, SMEM_BYTES>>>(
        ths, CID, bP, P_P, phs, CID, bP, P_P,
        NN, NN, CID, nullptr, f, nullptr, nullptr, NN, bF, nullptr);

    softmax_split<<<ROWS_TOT, blk256>>>(f, as, as + P_F);

    hm_gemm<0, false><<<dim3(CID / 128, NTILE_M, NB), blk128, SMEM_BYTES>>>(
        as, NN, bF, P_F, gTs, NN, bP, P_P,
        NN, CID, NN, nullptr, nullptr, ys, ys + P_P, CID, bP, nullptr);

    hm_gemm<1, true><<<dim3(CC / 128, NTILE_M, NB), blk128, SMEM_BYTES>>>(
        ys, CID, bP, P_P, wzw, CID, 0, P_W,
        NN, CC, CID, wz_b, wy, nullptr, nullptr, CC, (size_t)NN * CC, part);

    bn_finalize<<<dim3(CC / 256), blk256>>>(gam, bet);
    out_kernel<<<dim3(NN / 32, CC / 32, NB), blkT>>>(wy, x1, out);
}

// round 15
// speedup vs baseline: 1.2846x; 1.2846x over previous
#include <cuda_runtime.h>
#include <cuda_bf16.h>
#include <cstdint>
#include <math.h>

// ---------------- problem constants ----------------
#define NB  8
#define CC  1024
#define CID 512
#define NN  3136
#define ROWS_TOT (NB * NN)
#define NTILE_M 25                 // ceil(3136/128)
#define BN_CHUNKS (NB * NTILE_M)   // 200

// ---------------- device scratch ----------------
static constexpr size_t P_X = (size_t)NB * NN * CC;
static constexpr size_t P_P = (size_t)NB * NN * CID;
static constexpr size_t P_W = (size_t)CID * CC;
static constexpr size_t P_F = (size_t)NB * NN * NN;

__device__ __nv_bfloat16 g_xs1[2 * P_X];
__device__ __nv_bfloat16 g_xs2[2 * P_X];
__device__ __nv_bfloat16 g_thw[2 * P_W];
__device__ __nv_bfloat16 g_phw[2 * P_W];
__device__ __nv_bfloat16 g_gw [2 * P_W];
__device__ __nv_bfloat16 g_wzw[2 * P_W];
__device__ __nv_bfloat16 g_ths[2 * P_P];
__device__ __nv_bfloat16 g_phs[2 * P_P];
__device__ __nv_bfloat16 g_gTs[2 * P_P];
__device__ __nv_bfloat16 g_ys [2 * P_P];
__device__ float g_f[P_F];
__device__ __nv_bfloat16 g_as[2 * P_F];
__device__ float g_wy[(size_t)NB * NN * CC];
__device__ float g_part[(size_t)BN_CHUNKS * CC * 2];
__device__ float g_ab[CC * 2];

// ---------------- mma / ldmatrix / cp.async wrappers ----------------
__device__ __forceinline__ void mma_bf16(float* c, const uint32_t* a,
                                         uint32_t b0, uint32_t b1)
{
    asm volatile(
        "mma.sync.aligned.m16n8k16.row.col.f32.bf16.bf16.f32 "
        "{%0,%1,%2,%3}, {%4,%5,%6,%7}, {%8,%9}, {%0,%1,%2,%3};"
        : "+f"(c[0]), "+f"(c[1]), "+f"(c[2]), "+f"(c[3])
        : "r"(a[0]), "r"(a[1]), "r"(a[2]), "r"(a[3]), "r"(b0), "r"(b1));
}

#define LDSM_X4(r, addr) \
    asm volatile("ldmatrix.sync.aligned.m8n8.x4.shared.b16 {%0,%1,%2,%3}, [%4];" \
        : "=r"((r)[0]), "=r"((r)[1]), "=r"((r)[2]), "=r"((r)[3]) : "r"(addr))

__device__ __forceinline__ void cp16(uint32_t dst, const void* src, int srcsize)
{
    asm volatile("cp.async.cg.shared.global [%0], [%1], 16, %2;"
        :: "r"(dst), "l"(src), "r"(srcsize));
}
#define CP_COMMIT() asm volatile("cp.async.commit_group;" ::: "memory")
#define CP_WAIT(n)  asm volatile("cp.async.wait_group %0;" :: "n"(n) : "memory")

// ---------------- fast exp (FMA pipe only, no MUFU) ----------------
// exp(x) for x <= 0 (softmax, max-subtracted). Rel error ~2.4e-6.
__device__ __forceinline__ float fexp(float x)
{
    float y = fmaxf(x * 1.4426950408889634f, -120.f);  // log2(e), clamp
    float n = rintf(y);
    float f = y - n;                                   // [-0.5, 0.5]
    float p = fmaf(f, 1.3333558146e-3f, 9.6181291e-3f);
    p = fmaf(f, p, 5.5504108664e-2f);
    p = fmaf(f, p, 2.4022650696e-1f);
    p = fmaf(f, p, 6.9314718056e-1f);
    p = fmaf(f, p, 1.0f);
    int e = (int)n;                                    // [-120, 0]
    return __int_as_float((e + 127) << 23) * p;
}

// ---------------- GEMM tiling: CTA 128x128, warp 64x32, K-step 32 ----------
#define STAGES 4
#define ROW_BYTES 80
#define A_BYTES (128 * ROW_BYTES)
#define STAGE_BYTES (2 * A_BYTES)
#define SMEM_BYTES (STAGES * STAGE_BYTES)   // 81920

// =====================================================================
// GEMM body: D(M x N) = 3-pass split-bf16 A(M,K) * B(N,K)^T
//   pass 0: A.hi*B.hi   pass 1: A.hi*B.lo   pass 2: A.lo*B.hi
// BIAS: 0 none, 1 col, 2 row.  BN: per-column (sum,sumsq) partials.
// Proven R10 configuration: 256 threads, warp 64x32, 2 CTAs/SM.
// =====================================================================
template <int BIAS, bool BN>
__device__ __forceinline__ void gemm_body(
    uint8_t* smraw,
    const __nv_bfloat16* __restrict__ A, int lda, size_t planeA2,
    const __nv_bfloat16* __restrict__ B, int ldb, size_t planeB2,
    int M, int N, int K,
    const float* __restrict__ bias,
    float* __restrict__ Cfb,
    __nv_bfloat16* __restrict__ Chb, __nv_bfloat16* __restrict__ Clb,
    int ldc, int m0, int n0, float* __restrict__ bnPart)
{
    const uint32_t smBase = (uint32_t)__cvta_generic_to_shared(smraw);
    const int tid  = threadIdx.x;
    const int wid  = tid >> 5;
    const int lane = tid & 31;
    const int gid  = lane >> 2;
    const int tig  = lane & 3;
    const int warp_m = (wid & 1) * 64;
    const int warp_n = (wid >> 1) * 32;

    const int lrow = tid >> 1;
    const int lcol = (tid & 1) * 32;
    const int aok = ((m0 + lrow) < M) ? 16 : 0;
    const int bok = ((n0 + lrow) < N) ? 16 : 0;
    const char* aRow = (const char*)(A + (size_t)(m0 + lrow) * lda);
    const char* bRow = (const char*)(B + (size_t)(n0 + lrow) * ldb);
    const uint32_t sA = lrow * ROW_BYTES + lcol;
    const uint32_t sB = A_BYTES + lrow * ROW_BYTES + lcol;

    const int kPerPass = K >> 5;
    const int nIter = 3 * kPerPass;

    const uint32_t aOff = (uint32_t)((warp_m + (lane & 15)) * ROW_BYTES + (lane >> 4) * 16);
    const uint32_t bOff = (uint32_t)(A_BYTES + (warp_n + (lane & 15)) * ROW_BYTES + (lane >> 4) * 16);

    float acc[4][4][4];
#pragma unroll
    for (int i = 0; i < 4; i++)
#pragma unroll
        for (int j = 0; j < 4; j++)
#pragma unroll
            for (int q = 0; q < 4; q++) acc[i][j][q] = 0.f;

    auto issue_stage = [&](int idx) {
        const int p  = idx / kPerPass;
        const int kc = idx - p * kPerPass;
        const size_t offA = (p == 2) ? planeA2 : 0;
        const size_t offB = (p == 1) ? planeB2 : 0;
        const uint32_t st = smBase + (uint32_t)(idx % STAGES) * STAGE_BYTES;
        const char* ga = aRow + offA + kc * 64 + lcol;
        const char* gb = bRow + offB + kc * 64 + lcol;
        cp16(st + sA,      ga,      aok);
        cp16(st + sA + 16, ga + 16, aok);
        cp16(st + sB,      gb,      bok);
        cp16(st + sB + 16, gb + 16, bok);
        CP_COMMIT();
    };

#pragma unroll
    for (int s = 0; s < STAGES - 1; s++) issue_stage(s);

    for (int it = 0; it < nIter; ++it) {
        CP_WAIT(STAGES - 2);
        __syncthreads();
        if (it + STAGES - 1 < nIter) issue_stage(it + STAGES - 1);
        else CP_COMMIT();

        const uint32_t st = smBase + (uint32_t)(it % STAGES) * STAGE_BYTES;
#pragma unroll
        for (int ks = 0; ks < 2; ks++) {
            uint32_t bp0[4], bp1[4];
            LDSM_X4(bp0, st + bOff + ks * 32);
            LDSM_X4(bp1, st + bOff + 1280 + ks * 32);
#pragma unroll
            for (int mf = 0; mf < 4; mf++) {
                uint32_t a[4];
                LDSM_X4(a, st + aOff + mf * 1280 + ks * 32);
                mma_bf16(acc[mf][0], a, bp0[0], bp0[2]);
                mma_bf16(acc[mf][1], a, bp0[1], bp0[3]);
                mma_bf16(acc[mf][2], a, bp1[0], bp1[2]);
                mma_bf16(acc[mf][3], a, bp1[1], bp1[3]);
            }
        }
    }

    // ---------------- epilogue ----------------
    float bs[8], bs2[8];
    if (BN) {
#pragma unroll
        for (int j = 0; j < 8; j++) { bs[j] = 0.f; bs2[j] = 0.f; }
    }

#pragma unroll
    for (int mf = 0; mf < 4; mf++) {
#pragma unroll
        for (int nf = 0; nf < 4; nf++) {
            const int col = n0 + warp_n + nf * 8 + tig * 2;
            if (col >= N) continue;
            float bcol0 = 0.f, bcol1 = 0.f;
            if (BIAS == 1) { bcol0 = bias[col]; bcol1 = bias[col + 1]; }
#pragma unroll
            for (int half = 0; half < 2; half++) {
                const int row = m0 + warp_m + mf * 16 + gid + half * 8;
                if (row >= M) continue;
                float v0 = acc[mf][nf][half * 2 + 0];
                float v1 = acc[mf][nf][half * 2 + 1];
                if (BIAS == 1) { v0 += bcol0; v1 += bcol1; }
                if (BIAS == 2) { float br = bias[row]; v0 += br; v1 += br; }
                if (BN) {
                    bs[nf * 2 + 0] += v0;  bs2[nf * 2 + 0] += v0 * v0;
                    bs[nf * 2 + 1] += v1;  bs2[nf * 2 + 1] += v1 * v1;
                }
                const size_t o = (size_t)row * ldc + col;
                if (Cfb) {
                    *(float2*)(Cfb + o) = make_float2(v0, v1);
                } else {
                    __nv_bfloat16 h0 = __float2bfloat16(v0);
                    __nv_bfloat16 h1 = __float2bfloat16(v1);
                    __nv_bfloat162 hh, ll;
                    hh.x = h0; hh.y = h1;
                    ll.x = __float2bfloat16(v0 - __bfloat162float(h0));
                    ll.y = __float2bfloat16(v1 - __bfloat162float(h1));
                    *(__nv_bfloat162*)(Chb + o) = hh;
                    *(__nv_bfloat162*)(Clb + o) = ll;
                }
            }
        }
    }

    if (BN) {
#pragma unroll
        for (int j = 0; j < 8; j++) {
#pragma unroll
            for (int off = 4; off < 32; off <<= 1) {
                bs[j]  += __shfl_xor_sync(0xffffffffu, bs[j],  off);
                bs2[j] += __shfl_xor_sync(0xffffffffu, bs2[j], off);
            }
        }
        __syncthreads();
        float* sum0 = (float*)smraw;
        float* sq0  = sum0 + 256;
        if (lane < 4) {
#pragma unroll
            for (int nf = 0; nf < 4; nf++) {
#pragma unroll
                for (int par = 0; par < 2; par++) {
                    int c = warp_n + nf * 8 + tig * 2 + par;
                    sum0[(wid & 1) * 128 + c] = bs[nf * 2 + par];
                    sq0 [(wid & 1) * 128 + c] = bs2[nf * 2 + par];
                }
            }
        }
        __syncthreads();
        if (tid < 128) {
            float s  = sum0[tid] + sum0[128 + tid];
            float s2 = sq0[tid]  + sq0[128 + tid];
            bnPart[(size_t)(n0 + tid) * 2 + 0] = s;
            bnPart[(size_t)(n0 + tid) * 2 + 1] = s2;
        }
    }
}

// =====================================================================
// kernels wrapping gemm_body
// =====================================================================
__global__ void __launch_bounds__(256, 2)
proj_gemm(const __nv_bfloat16* __restrict__ xs1, const __nv_bfloat16* __restrict__ xs2,
          const __nv_bfloat16* __restrict__ thw, const __nv_bfloat16* __restrict__ phw,
          const __nv_bfloat16* __restrict__ gw,
          const float* __restrict__ th_b, const float* __restrict__ ph_b,
          const float* __restrict__ g_b,
          __nv_bfloat16* __restrict__ ths, __nv_bfloat16* __restrict__ phs,
          __nv_bfloat16* __restrict__ gTs)
{
    extern __shared__ __align__(16) uint8_t smraw[];
    const int z = blockIdx.z;
    const int which = z % 3;
    const int bz = z / 3;
    const size_t bX = (size_t)NN * CC;
    const size_t bP = (size_t)NN * CID;

    if (which == 0) {
        gemm_body<1, false>(smraw,
            xs1 + (size_t)bz * bX, CC, P_X * 2,
            thw, CC, P_W * 2,
            NN, CID, CC, th_b,
            nullptr, ths + (size_t)bz * bP, ths + P_P + (size_t)bz * bP,
            CID, blockIdx.y * 128, blockIdx.x * 128, nullptr);
    } else if (which == 1) {
        gemm_body<1, false>(smraw,
            xs2 + (size_t)bz * bX, CC, P_X * 2,
            phw, CC, P_W * 2,
            NN, CID, CC, ph_b,
            nullptr, phs + (size_t)bz * bP, phs + P_P + (size_t)bz * bP,
            CID, blockIdx.y * 128, blockIdx.x * 128, nullptr);
    } else {
        gemm_body<2, false>(smraw,
            gw, CC, P_W * 2,
            xs2 + (size_t)bz * bX, CC, P_X * 2,
            CID, NN, CC, g_b,
            nullptr, gTs + (size_t)bz * bP, gTs + P_P + (size_t)bz * bP,
            NN, blockIdx.x * 128, blockIdx.y * 128, nullptr);
    }
}

template <int BIAS, bool BN>
__global__ void __launch_bounds__(256, 2)
hm_gemm(const __nv_bfloat16* __restrict__ A, int lda, size_t batchA, size_t planeA,
        const __nv_bfloat16* __restrict__ B, int ldb, size_t batchB, size_t planeB,
        int M, int N, int K,
        const float* __restrict__ bias,
        float* __restrict__ Cf,
        __nv_bfloat16* __restrict__ Chi, __nv_bfloat16* __restrict__ Clo,
        int ldc, size_t batchC, float* __restrict__ bnPart)
{
    extern __shared__ __align__(16) uint8_t smraw[];
    const int bz = blockIdx.z;
    const int m0 = blockIdx.y * 128;
    const int n0 = blockIdx.x * 128;
    float* bp = nullptr;
    if (BN) bp = bnPart + ((size_t)bz * NTILE_M + blockIdx.y) * CC * 2;
    gemm_body<BIAS, BN>(smraw,
        A + (size_t)bz * batchA, lda, planeA * 2,
        B + (size_t)bz * batchB, ldb, planeB * 2,
        M, N, K, bias,
        Cf ? Cf + (size_t)bz * batchC : nullptr,
        Chi ? Chi + (size_t)bz * batchC : nullptr,
        Clo ? Clo + (size_t)bz * batchC : nullptr,
        ldc, m0, n0, bp);
}

// =====================================================================
// NCHW -> NHWC transpose + bf16 hi/lo split of x1 and x2
// =====================================================================
__global__ void __launch_bounds__(256)
split_tr(const float* __restrict__ x1, const float* __restrict__ x2,
         __nv_bfloat16* __restrict__ hi1, __nv_bfloat16* __restrict__ hi2)
{
    __shared__ float t[32][33];
    const int z = blockIdx.z;
    const int b = z & 7;
    const float* x = (z < NB) ? x1 : x2;
    __nv_bfloat16* hi = (z < NB) ? hi1 : hi2;
    const int n0 = blockIdx.x * 32;
    const int c0 = blockIdx.y * 32;
    const int tx = threadIdx.x, ty = threadIdx.y;

    for (int i = ty; i < 32; i += 8)
        t[i][tx] = x[((size_t)b * CC + c0 + i) * NN + n0 + tx];
    __syncthreads();
    for (int i = ty; i < 32; i += 8) {
        float v = t[tx][i];
        size_t o = ((size_t)b * NN + n0 + i) * CC + c0 + tx;
        __nv_bfloat16 h = __float2bfloat16(v);
        hi[o] = h;
        hi[P_X + o] = __float2bfloat16(v - __bfloat162float(h));
    }
}

__global__ void __launch_bounds__(256)
split_w4(const float* __restrict__ w0, const float* __restrict__ w1,
         const float* __restrict__ w2, const float* __restrict__ w3,
         __nv_bfloat16* __restrict__ h0, __nv_bfloat16* __restrict__ h1,
         __nv_bfloat16* __restrict__ h2, __nv_bfloat16* __restrict__ h3)
{
    const int which = blockIdx.y;
    const float* w = which == 0 ? w0 : which == 1 ? w1 : which == 2 ? w2 : w3;
    __nv_bfloat16* h = which == 0 ? h0 : which == 1 ? h1 : which == 2 ? h2 : h3;
    int i = blockIdx.x * 256 + threadIdx.x;
    if (i < (int)P_W) {
        float v = w[i];
        __nv_bfloat16 hh = __float2bfloat16(v);
        h[i] = hh;
        h[P_W + i] = __float2bfloat16(v - __bfloat162float(hh));
    }
}

// =====================================================================
// Row softmax over NN (vectorized, FMA-pipe exp), writes split bf16 attn
// =====================================================================
#define NN4 (NN / 4)
__global__ void __launch_bounds__(256)
softmax_split(const float* __restrict__ F, __nv_bfloat16* __restrict__ hi,
              __nv_bfloat16* __restrict__ lo)
{
    __shared__ float4 buf[NN4];
    __shared__ float red[256];
    const size_t row = blockIdx.x;
    const float4* __restrict__ p = (const float4*)(F + row * (size_t)NN);
    const int t = threadIdx.x;

    float m = -3.402823466e38f;
    for (int i = t; i < NN4; i += 256) {
        float4 v = p[i];
        buf[i] = v;
        m = fmaxf(fmaxf(m, fmaxf(v.x, v.y)), fmaxf(v.z, v.w));
    }
    red[t] = m; __syncthreads();
    for (int s = 128; s > 0; s >>= 1) {
        if (t < s) red[t] = fmaxf(red[t], red[t + s]);
        __syncthreads();
    }
    m = red[0];
    __syncthreads();

    float sum = 0.f;
    for (int i = t; i < NN4; i += 256) {
        float4 v = buf[i];
        v.x = fexp(v.x - m); v.y = fexp(v.y - m);
        v.z = fexp(v.z - m); v.w = fexp(v.w - m);
        buf[i] = v;
        sum += (v.x + v.y) + (v.z + v.w);
    }
    red[t] = sum; __syncthreads();
    for (int s = 128; s > 0; s >>= 1) {
        if (t < s) red[t] += red[t + s];
        __syncthreads();
    }
    const float inv = 1.f / red[0];
    __nv_bfloat162* __restrict__ hp = (__nv_bfloat162*)(hi + row * (size_t)NN);
    __nv_bfloat162* __restrict__ lp = (__nv_bfloat162*)(lo + row * (size_t)NN);
    for (int i = t; i < NN4; i += 256) {
        float4 v = buf[i];
        float a0 = v.x * inv, a1 = v.y * inv, a2 = v.z * inv, a3 = v.w * inv;
        __nv_bfloat162 h0, h1, l0, l1;
        h0.x = __float2bfloat16(a0); h0.y = __float2bfloat16(a1);
        h1.x = __float2bfloat16(a2); h1.y = __float2bfloat16(a3);
        l0.x = __float2bfloat16(a0 - __bfloat162float(h0.x));
        l0.y = __float2bfloat16(a1 - __bfloat162float(h0.y));
        l1.x = __float2bfloat16(a2 - __bfloat162float(h1.x));
        l1.y = __float2bfloat16(a3 - __bfloat162float(h1.y));
        hp[i * 2] = h0; hp[i * 2 + 1] = h1;
        lp[i * 2] = l0; lp[i * 2 + 1] = l1;
    }
}

// =====================================================================
// BN finalize over fused partials
// =====================================================================
__global__ void __launch_bounds__(256)
bn_finalize(const float* __restrict__ gamma, const float* __restrict__ beta)
{
    int c = blockIdx.x * 256 + threadIdx.x;
    float s = 0.f, s2 = 0.f;
    for (int ch = 0; ch < BN_CHUNKS; ch++) {
        s  += g_part[((size_t)ch * CC + c) * 2 + 0];
        s2 += g_part[((size_t)ch * CC + c) * 2 + 1];
    }
    const float invR = 1.f / (float)ROWS_TOT;
    float mu  = s * invR;
    float var = s2 * invR - mu * mu;
    float a = gamma[c] * rsqrtf(var + 1e-5f);
    g_ab[c * 2 + 0] = a;
    g_ab[c * 2 + 1] = beta[c] - mu * a;
}

// =====================================================================
// normalize + residual + NHWC->NCHW transpose
// =====================================================================
__global__ void __launch_bounds__(256)
out_kernel(const float* __restrict__ wy, const float* __restrict__ x1,
           float* __restrict__ out)
{
    __shared__ float tile[32][33];
    int b  = blockIdx.z;
    int n0 = blockIdx.x * 32;
    int c0 = blockIdx.y * 32;
    int tx = threadIdx.x, ty = threadIdx.y;

    for (int i = ty; i < 32; i += 8) {
        int c = c0 + tx, n = n0 + i;
        float v = wy[((size_t)b * NN + n) * CC + c];
        tile[i][tx] = v * g_ab[c * 2 + 0] + g_ab[c * 2 + 1];
    }
    __syncthreads();
    for (int i = ty; i < 32; i += 8) {
        int c = c0 + i, n = n0 + tx;
        size_t idx = ((size_t)b * CC + c) * (size_t)NN + n;
        out[idx] = tile[tx][i] + x1[idx];
    }
}

// =====================================================================
// launcher
// =====================================================================
extern "C" void kernel_launch(void* const* d_in, const int* in_sizes, int n_in,
                              void* d_out, int out_size)
{
    const float* x1   = (const float*)d_in[0];
    const float* x2   = (const float*)d_in[1];
    const float* g_w  = (const float*)d_in[2];
    const float* g_b  = (const float*)d_in[3];
    const float* th_w = (const float*)d_in[4];
    const float* th_b = (const float*)d_in[5];
    const float* ph_w = (const float*)d_in[6];
    const float* ph_b = (const float*)d_in[7];
    const float* wz_w = (const float*)d_in[8];
    const float* wz_b = (const float*)d_in[9];
    const float* gam  = (const float*)d_in[10];
    const float* bet  = (const float*)d_in[11];
    float* out = (float*)d_out;

    cudaFuncSetAttribute((const void*)proj_gemm,
                         cudaFuncAttributeMaxDynamicSharedMemorySize, SMEM_BYTES);
    cudaFuncSetAttribute((const void*)hm_gemm<0, false>,
                         cudaFuncAttributeMaxDynamicSharedMemorySize, SMEM_BYTES);
    cudaFuncSetAttribute((const void*)hm_gemm<1, true>,
                         cudaFuncAttributeMaxDynamicSharedMemorySize, SMEM_BYTES);

    __nv_bfloat16 *xs1, *xs2, *thw, *phw, *gw, *wzw, *ths, *phs, *gTs, *ys, *as;
    float *f, *wy, *part;
    cudaGetSymbolAddress((void**)&xs1, g_xs1);
    cudaGetSymbolAddress((void**)&xs2, g_xs2);
    cudaGetSymbolAddress((void**)&thw, g_thw);
    cudaGetSymbolAddress((void**)&phw, g_phw);
    cudaGetSymbolAddress((void**)&gw,  g_gw);
    cudaGetSymbolAddress((void**)&wzw, g_wzw);
    cudaGetSymbolAddress((void**)&ths, g_ths);
    cudaGetSymbolAddress((void**)&phs, g_phs);
    cudaGetSymbolAddress((void**)&gTs, g_gTs);
    cudaGetSymbolAddress((void**)&ys,  g_ys);
    cudaGetSymbolAddress((void**)&as,  g_as);
    cudaGetSymbolAddress((void**)&f,   g_f);
    cudaGetSymbolAddress((void**)&wy,  g_wy);
    cudaGetSymbolAddress((void**)&part, g_part);

    dim3 blk256(256);
    dim3 blkT(32, 8);

    split_tr<<<dim3(NN / 32, CC / 32, 2 * NB), blkT>>>(x1, x2, xs1, xs2);
    split_w4<<<dim3((int)((P_W + 255) / 256), 4), blk256>>>(
        th_w, ph_w, g_w, wz_w, thw, phw, gw, wzw);

    const size_t bP = (size_t)NN * CID;
    const size_t bF = (size_t)NN * NN;

    proj_gemm<<<dim3(CID / 128, NTILE_M, NB * 3), blk256, SMEM_BYTES>>>(
        xs1, xs2, thw, phw, gw, th_b, ph_b, g_b, ths, phs, gTs);

    hm_gemm<0, false><<<dim3(NTILE_M, NTILE_M, NB), blk256, SMEM_BYTES>>>(
        ths, CID, bP, P_P, phs, CID, bP, P_P,
        NN, NN, CID, nullptr, f, nullptr, nullptr, NN, bF, nullptr);

    softmax_split<<<ROWS_TOT, blk256>>>(f, as, as + P_F);

    hm_gemm<0, false><<<dim3(CID / 128, NTILE_M, NB), blk256, SMEM_BYTES>>>(
        as, NN, bF, P_F, gTs, NN, bP, P_P,
        NN, CID, NN, nullptr, nullptr, ys, ys + P_P, CID, bP, nullptr);

    hm_gemm<1, true><<<dim3(CC / 128, NTILE_M, NB), blk256, SMEM_BYTES>>>(
        ys, CID, bP, P_P, wzw, CID, 0, P_W,
        NN, CC, CID, wz_b, wy, nullptr, nullptr, CC, (size_t)NN * CC, part);

    bn_finalize<<<dim3(CC / 256), blk256>>>(gam, bet);
    out_kernel<<<dim3(NN / 32, CC / 32, NB), blkT>>>(wy, x1, out);
}